// round 1
// baseline (speedup 1.0000x reference)
#include <cuda_runtime.h>
#include <cuda_bf16.h>

#define HID      64
#define SC_DIMS  6
#define EDGE_DIM 16
#define MSG_IN   156
#define MAXN     100000

// ---------------- scratch (device globals; no allocations) ----------------
__device__ __align__(16) float g_h[MAXN * HID];
__device__ __align__(16) float g_Ps[MAXN * HID];
__device__ __align__(16) float g_Pd[MAXN * HID];
__device__ __align__(16) float g_agg[MAXN * HID];
__device__ float g_wdeg[MAXN];

#define USE_RED_V4 1

__device__ __forceinline__ void red_add_v4(float* p, float4 v) {
#if USE_RED_V4
    asm volatile("red.global.add.v4.f32 [%0], {%1,%2,%3,%4};"
                 :: "l"(p), "f"(v.x), "f"(v.y), "f"(v.z), "f"(v.w) : "memory");
#else
    atomicAdd(p + 0, v.x); atomicAdd(p + 1, v.y);
    atomicAdd(p + 2, v.z); atomicAdd(p + 3, v.w);
#endif
}

// ---------------- clears ----------------
__global__ void k_clear_agg(int n) {
    int i = blockIdx.x * blockDim.x + threadIdx.x;
    if (i < n) g_agg[i] = 0.f;
}
__global__ void k_clear_wdeg(int n) {
    int i = blockIdx.x * blockDim.x + threadIdx.x;
    if (i < n) g_wdeg[i] = 0.f;
}
__global__ void k_clear_out(float* __restrict__ p, int n) {
    int i = blockIdx.x * blockDim.x + threadIdx.x;
    if (i < n) p[i] = 0.f;
}

// ---------------- weighted degree (ew is static across layers) ----------------
__global__ void k_wdeg(const int* __restrict__ el, const float* __restrict__ ew, int n_edges) {
    int e = blockIdx.x * blockDim.x + threadIdx.x;
    if (e < n_edges) atomicAdd(&g_wdeg[el[2 * e + 1]], ew[e]);
}

// ---------------- h = x @ lin_w + lin_b ----------------
__global__ __launch_bounds__(256) void k_lin(const float* __restrict__ x,
                                             const float* __restrict__ W,
                                             const float* __restrict__ b, int n_nodes) {
    __shared__ float sW[64 * 64];
    for (int i = threadIdx.x; i < 64 * 64; i += blockDim.x) sW[i] = W[i];
    __syncthreads();
    const int lane = threadIdx.x & 31;
    const int wid  = blockIdx.x * (blockDim.x >> 5) + (threadIdx.x >> 5);
    const int nw   = gridDim.x * (blockDim.x >> 5);
    const float b0 = b[lane], b1 = b[lane + 32];
    const int ntiles = (n_nodes + 3) >> 2;
    for (int t = wid; t < ntiles; t += nw) {
        const int n0 = t * 4;
        float xr[4][2], a0[4], a1[4];
#pragma unroll
        for (int nn = 0; nn < 4; nn++) {
            int n = min(n0 + nn, n_nodes - 1);
            xr[nn][0] = x[n * 64 + lane];
            xr[nn][1] = x[n * 64 + lane + 32];
            a0[nn] = b0; a1[nn] = b1;
        }
#pragma unroll
        for (int r = 0; r < 2; r++)
#pragma unroll
            for (int kk = 0; kk < 32; kk++) {
                const float* wr = &sW[(r * 32 + kk) * 64];
                float w0 = wr[lane], w1 = wr[lane + 32];
#pragma unroll
                for (int nn = 0; nn < 4; nn++) {
                    float xv = __shfl_sync(0xffffffffu, xr[nn][r], kk);
                    a0[nn] += xv * w0; a1[nn] += xv * w1;
                }
            }
#pragma unroll
        for (int nn = 0; nn < 4; nn++) {
            int n = n0 + nn;
            if (n < n_nodes) { g_h[n * 64 + lane] = a0[nn]; g_h[n * 64 + lane + 32] = a1[nn]; }
        }
    }
}

// ---------------- per-node partial products for the edge MLP ----------------
// P_src[n] = h[n]@W1[0:64]  + sc[n]@W1[128:134]
// P_dst[n] = h[n]@W1[64:128] + sc[n]@W1[134:140] + b1
__global__ __launch_bounds__(256) void k_pair(const int* __restrict__ nstruct,
                                              const float* __restrict__ w1,
                                              const float* __restrict__ b1,
                                              int layer, int n_nodes) {
    __shared__ float sWs[70 * 64];
    __shared__ float sWd[70 * 64];
    const float* Wl = w1 + (size_t)layer * MSG_IN * 64;
    for (int i = threadIdx.x; i < 70 * 64; i += blockDim.x) {
        int r = i >> 6, j = i & 63;
        int rs = (r < 64) ? r : (128 + (r - 64));
        int rd = (r < 64) ? (64 + r) : (134 + (r - 64));
        sWs[i] = Wl[rs * 64 + j];
        sWd[i] = Wl[rd * 64 + j];
    }
    __syncthreads();
    const int lane = threadIdx.x & 31;
    const int wid  = blockIdx.x * (blockDim.x >> 5) + (threadIdx.x >> 5);
    const int nw   = gridDim.x * (blockDim.x >> 5);
    const float bd0 = b1[layer * 64 + lane], bd1 = b1[layer * 64 + lane + 32];
    const int ntiles = (n_nodes + 3) >> 2;
    for (int t = wid; t < ntiles; t += nw) {
        const int n0 = t * 4;
        float xr[4][2], as0[4], as1[4], ad0[4], ad1[4];
        float scr;
        {
            int nn = lane / 6, c = lane - nn * 6;
            int n = min(n0 + min(nn, 3), n_nodes - 1);
            scr = (lane < 24) ? (float)nstruct[n * SC_DIMS + c] : 0.f;
        }
#pragma unroll
        for (int nn = 0; nn < 4; nn++) {
            int n = min(n0 + nn, n_nodes - 1);
            xr[nn][0] = g_h[n * 64 + lane];
            xr[nn][1] = g_h[n * 64 + lane + 32];
            as0[nn] = 0.f; as1[nn] = 0.f; ad0[nn] = bd0; ad1[nn] = bd1;
        }
#pragma unroll
        for (int r = 0; r < 2; r++)
#pragma unroll
            for (int kk = 0; kk < 32; kk++) {
                int k = r * 32 + kk;
                float ws0 = sWs[k * 64 + lane], ws1 = sWs[k * 64 + lane + 32];
                float wd0 = sWd[k * 64 + lane], wd1 = sWd[k * 64 + lane + 32];
#pragma unroll
                for (int nn = 0; nn < 4; nn++) {
                    float xv = __shfl_sync(0xffffffffu, xr[nn][r], kk);
                    as0[nn] += xv * ws0; as1[nn] += xv * ws1;
                    ad0[nn] += xv * wd0; ad1[nn] += xv * wd1;
                }
            }
#pragma unroll
        for (int c = 0; c < 6; c++) {
            int k = 64 + c;
            float ws0 = sWs[k * 64 + lane], ws1 = sWs[k * 64 + lane + 32];
            float wd0 = sWd[k * 64 + lane], wd1 = sWd[k * 64 + lane + 32];
#pragma unroll
            for (int nn = 0; nn < 4; nn++) {
                float sv = __shfl_sync(0xffffffffu, scr, nn * 6 + c);
                as0[nn] += sv * ws0; as1[nn] += sv * ws1;
                ad0[nn] += sv * wd0; ad1[nn] += sv * wd1;
            }
        }
#pragma unroll
        for (int nn = 0; nn < 4; nn++) {
            int n = n0 + nn;
            if (n < n_nodes) {
                g_Ps[n * 64 + lane] = as0[nn]; g_Ps[n * 64 + lane + 32] = as1[nn];
                g_Pd[n * 64 + lane] = ad0[nn]; g_Pd[n * 64 + lane + 32] = ad1[nn];
            }
        }
    }
}

// ---------------- edge kernel: agg[dst] += ew * relu(Ps[src]+Pd[dst]+ef@E) ----------------
__global__ __launch_bounds__(256) void k_edge(const int* __restrict__ el,
                                              const float* __restrict__ ef,
                                              const float* __restrict__ ew,
                                              const float* __restrict__ w1,
                                              int layer, int n_edges) {
    const int lane = threadIdx.x & 31;
    const int warp = threadIdx.x >> 5;
    // E = W1 rows [140:156), kept in registers per lane
    float E0[16], E1[16];
    const float* Wb = w1 + ((size_t)layer * MSG_IN + 140) * 64;
#pragma unroll
    for (int k = 0; k < 16; k++) { E0[k] = Wb[k * 64 + lane]; E1[k] = Wb[k * 64 + lane + 32]; }
    __shared__ float stage[8][64];
    int gw = blockIdx.x * 8 + warp;
    int nw = gridDim.x * 8;
    for (int e = gw; e < n_edges; e += nw) {
        int2 sd = ((const int2*)el)[e];
        const int src = sd.x, dst = sd.y;
        const float w = ew[e];
        float efv = (lane < 16) ? ef[(size_t)e * 16 + lane] : 0.f;
        float a0 = g_Ps[(size_t)src * 64 + lane]      + g_Pd[(size_t)dst * 64 + lane];
        float a1 = g_Ps[(size_t)src * 64 + lane + 32] + g_Pd[(size_t)dst * 64 + lane + 32];
#pragma unroll
        for (int k = 0; k < 16; k++) {
            float v = __shfl_sync(0xffffffffu, efv, k);
            a0 += v * E0[k]; a1 += v * E1[k];
        }
        a0 = fmaxf(a0, 0.f) * w;
        a1 = fmaxf(a1, 0.f) * w;
        stage[warp][lane] = a0;
        stage[warp][lane + 32] = a1;
        __syncwarp();
        if (lane < 16) {
            float4 v = ((const float4*)stage[warp])[lane];
            red_add_v4(&g_agg[(size_t)dst * 64 + lane * 4], v);
        }
        __syncwarp();
    }
}

// ---------------- upd = agg @ W2 + b2*wdeg   (in place into g_agg) ----------------
__global__ __launch_bounds__(256) void k_node_a(const float* __restrict__ w2,
                                                const float* __restrict__ b2,
                                                int layer, int n_nodes) {
    __shared__ float sW[64 * 64];
    const float* Wl = w2 + (size_t)layer * 64 * 64;
    for (int i = threadIdx.x; i < 64 * 64; i += blockDim.x) sW[i] = Wl[i];
    __syncthreads();
    const int lane = threadIdx.x & 31;
    const int wid  = blockIdx.x * (blockDim.x >> 5) + (threadIdx.x >> 5);
    const int nw   = gridDim.x * (blockDim.x >> 5);
    const float b0 = b2[layer * 64 + lane], b1 = b2[layer * 64 + lane + 32];
    const int ntiles = (n_nodes + 3) >> 2;
    for (int t = wid; t < ntiles; t += nw) {
        const int n0 = t * 4;
        float xr[4][2], a0[4], a1[4];
#pragma unroll
        for (int nn = 0; nn < 4; nn++) {
            int n = min(n0 + nn, n_nodes - 1);
            xr[nn][0] = g_agg[n * 64 + lane];
            xr[nn][1] = g_agg[n * 64 + lane + 32];
            float wd = g_wdeg[n];
            a0[nn] = b0 * wd; a1[nn] = b1 * wd;
        }
#pragma unroll
        for (int r = 0; r < 2; r++)
#pragma unroll
            for (int kk = 0; kk < 32; kk++) {
                const float* wr = &sW[(r * 32 + kk) * 64];
                float w0 = wr[lane], w1 = wr[lane + 32];
#pragma unroll
                for (int nn = 0; nn < 4; nn++) {
                    float xv = __shfl_sync(0xffffffffu, xr[nn][r], kk);
                    a0[nn] += xv * w0; a1[nn] += xv * w1;
                }
            }
#pragma unroll
        for (int nn = 0; nn < 4; nn++) {
            int n = n0 + nn;
            if (n < n_nodes) { g_agg[n * 64 + lane] = a0[nn]; g_agg[n * 64 + lane + 32] = a1[nn]; }
        }
    }
}

// ---------------- h = relu( relu(cat(h,upd)@U1 + ub1) @ U2 + ub2 )  (in place) -------------
__global__ __launch_bounds__(256) void k_node_bc(const float* __restrict__ u1,
                                                 const float* __restrict__ ub1,
                                                 const float* __restrict__ u2,
                                                 const float* __restrict__ ub2,
                                                 int layer, int n_nodes) {
    __shared__ float sU1[128 * 64];   // 32 KB
    __shared__ float sU2[64 * 64];    // 16 KB
    const float* U1l = u1 + (size_t)layer * 128 * 64;
    const float* U2l = u2 + (size_t)layer * 64 * 64;
    for (int i = threadIdx.x; i < 128 * 64; i += blockDim.x) sU1[i] = U1l[i];
    for (int i = threadIdx.x; i < 64 * 64; i += blockDim.x) sU2[i] = U2l[i];
    __syncthreads();
    const int lane = threadIdx.x & 31;
    const int wid  = blockIdx.x * (blockDim.x >> 5) + (threadIdx.x >> 5);
    const int nw   = gridDim.x * (blockDim.x >> 5);
    const float c10 = ub1[layer * 64 + lane], c11 = ub1[layer * 64 + lane + 32];
    const float c20 = ub2[layer * 64 + lane], c21 = ub2[layer * 64 + lane + 32];
    const int ntiles = (n_nodes + 3) >> 2;
    for (int t = wid; t < ntiles; t += nw) {
        const int n0 = t * 4;
        float hr[4][2], ur[4][2], a0[4], a1[4];
#pragma unroll
        for (int nn = 0; nn < 4; nn++) {
            int n = min(n0 + nn, n_nodes - 1);
            hr[nn][0] = g_h[n * 64 + lane];   hr[nn][1] = g_h[n * 64 + lane + 32];
            ur[nn][0] = g_agg[n * 64 + lane]; ur[nn][1] = g_agg[n * 64 + lane + 32];
            a0[nn] = c10; a1[nn] = c11;
        }
        // cat(h, upd) @ U1 : rows 0..63 with h, rows 64..127 with upd
#pragma unroll
        for (int r = 0; r < 2; r++)
#pragma unroll
            for (int kk = 0; kk < 32; kk++) {
                const float* wr = &sU1[(r * 32 + kk) * 64];
                float w0 = wr[lane], w1 = wr[lane + 32];
#pragma unroll
                for (int nn = 0; nn < 4; nn++) {
                    float xv = __shfl_sync(0xffffffffu, hr[nn][r], kk);
                    a0[nn] += xv * w0; a1[nn] += xv * w1;
                }
            }
#pragma unroll
        for (int r = 0; r < 2; r++)
#pragma unroll
            for (int kk = 0; kk < 32; kk++) {
                const float* wr = &sU1[(64 + r * 32 + kk) * 64];
                float w0 = wr[lane], w1 = wr[lane + 32];
#pragma unroll
                for (int nn = 0; nn < 4; nn++) {
                    float xv = __shfl_sync(0xffffffffu, ur[nn][r], kk);
                    a0[nn] += xv * w0; a1[nn] += xv * w1;
                }
            }
        // t = relu(.)  (reuse hr as t-fragments)
#pragma unroll
        for (int nn = 0; nn < 4; nn++) {
            hr[nn][0] = fmaxf(a0[nn], 0.f);
            hr[nn][1] = fmaxf(a1[nn], 0.f);
            a0[nn] = c20; a1[nn] = c21;
        }
        // t @ U2
#pragma unroll
        for (int r = 0; r < 2; r++)
#pragma unroll
            for (int kk = 0; kk < 32; kk++) {
                const float* wr = &sU2[(r * 32 + kk) * 64];
                float w0 = wr[lane], w1 = wr[lane + 32];
#pragma unroll
                for (int nn = 0; nn < 4; nn++) {
                    float xv = __shfl_sync(0xffffffffu, hr[nn][r], kk);
                    a0[nn] += xv * w0; a1[nn] += xv * w1;
                }
            }
#pragma unroll
        for (int nn = 0; nn < 4; nn++) {
            int n = n0 + nn;
            if (n < n_nodes) {
                g_h[n * 64 + lane]      = fmaxf(a0[nn], 0.f);
                g_h[n * 64 + lane + 32] = fmaxf(a1[nn], 0.f);
            }
        }
    }
}

// ---------------- outputs: graph_feature (atomic segsum) + node_feature copy -------------
__global__ void k_final(const int* __restrict__ n2g, float* __restrict__ out,
                        int n_nodes, int gf_floats) {
    int i = blockIdx.x * blockDim.x + threadIdx.x;
    int total = n_nodes * 16;
    if (i >= total) return;
    int n = i >> 4, q = i & 15;
    float4 v = ((const float4*)g_h)[i];
    ((float4*)out)[(gf_floats >> 2) + i] = v;   // node_feature block
    int g = n2g[n];
    red_add_v4(out + g * 64 + q * 4, v);        // graph_feature block
}

// ============================ launcher ============================
extern "C" void kernel_launch(void* const* d_in, const int* in_sizes, int n_in,
                              void* d_out, int out_size) {
    const float* x     = (const float*)d_in[0];
    const int*   el    = (const int*)d_in[1];
    const int*   ns    = (const int*)d_in[2];
    const float* ef    = (const float*)d_in[3];
    const float* ew    = (const float*)d_in[4];
    const int*   n2g   = (const int*)d_in[5];
    // d_in[6] = num_graphs scalar (value implied by out_size)
    const float* lin_w = (const float*)d_in[7];
    const float* lin_b = (const float*)d_in[8];
    const float* mw1   = (const float*)d_in[9];
    const float* mb1   = (const float*)d_in[10];
    const float* mw2   = (const float*)d_in[11];
    const float* mb2   = (const float*)d_in[12];
    const float* uw1   = (const float*)d_in[13];
    const float* ub1   = (const float*)d_in[14];
    const float* uw2   = (const float*)d_in[15];
    const float* ub2   = (const float*)d_in[16];

    const int n_nodes = in_sizes[0] / HID;
    const int n_edges = in_sizes[1] / 2;
    const int gf      = out_size - n_nodes * HID;   // graph_feature floats (128*64)
    float* out = (float*)d_out;

    auto cdiv = [](int a, int b) { return (a + b - 1) / b; };

    k_clear_wdeg<<<cdiv(n_nodes, 256), 256>>>(n_nodes);
    k_clear_out<<<cdiv(gf, 256), 256>>>(out, gf);
    k_wdeg<<<cdiv(n_edges, 256), 256>>>(el, ew, n_edges);
    k_lin<<<1184, 256>>>(x, lin_w, lin_b, n_nodes);

    for (int l = 0; l < 2; l++) {
        k_pair<<<740, 256>>>(ns, mw1, mb1, l, n_nodes);
        k_clear_agg<<<cdiv(n_nodes * HID, 256), 256>>>(n_nodes * HID);
        k_edge<<<4096, 256>>>(el, ef, ew, mw1, l, n_edges);
        k_node_a<<<1184, 256>>>(mw2, mb2, l, n_nodes);
        k_node_bc<<<592, 256>>>(uw1, ub1, uw2, ub2, l, n_nodes);
    }

    k_final<<<cdiv(n_nodes * 16, 256), 256>>>(n2g, out, n_nodes, gf);
}

// round 2
// speedup vs baseline: 1.2382x; 1.2382x over previous
#include <cuda_runtime.h>
#include <cuda_bf16.h>

#define HID      64
#define SC_DIMS  6
#define EDGE_DIM 16
#define MSG_IN   156
#define MAXN     100000
#define MAXE     1600000
#define SCHUNK   1024

// ---------------- scratch (device globals; no allocations) ----------------
__device__ __align__(16) float g_h[MAXN * HID];
__device__ __align__(16) float g_Ps[MAXN * HID];
__device__ __align__(16) float g_Pd[MAXN * HID];
__device__ __align__(16) float g_agg[MAXN * HID];
__device__ float g_wdeg[MAXN];

// CSR build scratch
__device__ int g_cnt[MAXN];
__device__ int g_ptr[MAXN];
__device__ int g_cur[MAXN];
__device__ int g_part[256];
__device__ __align__(16) int4 g_csre[MAXE];   // {src, eid, ew_bits, 0}

__device__ __forceinline__ void red_add_v4(float* p, float4 v) {
    asm volatile("red.global.add.v4.f32 [%0], {%1,%2,%3,%4};"
                 :: "l"(p), "f"(v.x), "f"(v.y), "f"(v.z), "f"(v.w) : "memory");
}

// ---------------- clears ----------------
__global__ void k_clear_cnt(int n) {
    int i = blockIdx.x * blockDim.x + threadIdx.x;
    if (i < n) g_cnt[i] = 0;
}
__global__ void k_clear_out(float* __restrict__ p, int n) {
    int i = blockIdx.x * blockDim.x + threadIdx.x;
    if (i < n) p[i] = 0.f;
}

// ---------------- CSR build: histogram -> scan -> scatter ----------------
__global__ void k_hist(const int* __restrict__ el, int n_edges) {
    int e = blockIdx.x * blockDim.x + threadIdx.x;
    if (e < n_edges) atomicAdd(&g_cnt[el[2 * e + 1]], 1);
}

__global__ __launch_bounds__(256) void k_scan1(int n) {
    __shared__ int sm[256];
    int base = blockIdx.x * SCHUNK;
    int s = 0;
    for (int j = threadIdx.x; j < SCHUNK; j += 256) {
        int i = base + j;
        s += (i < n) ? g_cnt[i] : 0;
    }
    sm[threadIdx.x] = s; __syncthreads();
    for (int off = 128; off; off >>= 1) {
        if (threadIdx.x < off) sm[threadIdx.x] += sm[threadIdx.x + off];
        __syncthreads();
    }
    if (threadIdx.x == 0) g_part[blockIdx.x] = sm[0];
}

__global__ void k_scan2(int nb) {
    if (threadIdx.x == 0 && blockIdx.x == 0) {
        int a = 0;
        for (int b = 0; b < nb; b++) { int t = g_part[b]; g_part[b] = a; a += t; }
    }
}

__global__ __launch_bounds__(256) void k_scan3(int n) {
    __shared__ int sm[256];
    int base = blockIdx.x * SCHUNK + threadIdx.x * 4;
    int c[4]; int s = 0;
#pragma unroll
    for (int j = 0; j < 4; j++) {
        int i = base + j;
        c[j] = (i < n) ? g_cnt[i] : 0;
        s += c[j];
    }
    sm[threadIdx.x] = s; __syncthreads();
    for (int off = 1; off < 256; off <<= 1) {
        int v = sm[threadIdx.x];
        int u = (threadIdx.x >= off) ? sm[threadIdx.x - off] : 0;
        __syncthreads();
        sm[threadIdx.x] = v + u;
        __syncthreads();
    }
    int excl = sm[threadIdx.x] - s + g_part[blockIdx.x];
#pragma unroll
    for (int j = 0; j < 4; j++) {
        int i = base + j;
        if (i < n) { g_ptr[i] = excl; g_cur[i] = excl; excl += c[j]; }
    }
}

__global__ void k_scatter(const int* __restrict__ el, const float* __restrict__ ew, int n_edges) {
    int e = blockIdx.x * blockDim.x + threadIdx.x;
    if (e < n_edges) {
        int2 sd = ((const int2*)el)[e];
        int pos = atomicAdd(&g_cur[sd.y], 1);
        g_csre[pos] = make_int4(sd.x, e, __float_as_int(ew[e]), 0);
    }
}

// ---------------- h = x @ lin_w + lin_b ----------------
__global__ __launch_bounds__(256) void k_lin(const float* __restrict__ x,
                                             const float* __restrict__ W,
                                             const float* __restrict__ b, int n_nodes) {
    __shared__ float sW[64 * 64];
    for (int i = threadIdx.x; i < 64 * 64; i += blockDim.x) sW[i] = W[i];
    __syncthreads();
    const int lane = threadIdx.x & 31;
    const int wid  = blockIdx.x * (blockDim.x >> 5) + (threadIdx.x >> 5);
    const int nw   = gridDim.x * (blockDim.x >> 5);
    const float b0 = b[lane], b1 = b[lane + 32];
    const int ntiles = (n_nodes + 3) >> 2;
    for (int t = wid; t < ntiles; t += nw) {
        const int n0 = t * 4;
        float xr[4][2], a0[4], a1[4];
#pragma unroll
        for (int nn = 0; nn < 4; nn++) {
            int n = min(n0 + nn, n_nodes - 1);
            xr[nn][0] = x[n * 64 + lane];
            xr[nn][1] = x[n * 64 + lane + 32];
            a0[nn] = b0; a1[nn] = b1;
        }
#pragma unroll
        for (int r = 0; r < 2; r++)
#pragma unroll
            for (int kk = 0; kk < 32; kk++) {
                const float* wr = &sW[(r * 32 + kk) * 64];
                float w0 = wr[lane], w1 = wr[lane + 32];
#pragma unroll
                for (int nn = 0; nn < 4; nn++) {
                    float xv = __shfl_sync(0xffffffffu, xr[nn][r], kk);
                    a0[nn] += xv * w0; a1[nn] += xv * w1;
                }
            }
#pragma unroll
        for (int nn = 0; nn < 4; nn++) {
            int n = n0 + nn;
            if (n < n_nodes) { g_h[n * 64 + lane] = a0[nn]; g_h[n * 64 + lane + 32] = a1[nn]; }
        }
    }
}

// ---------------- per-node partial products for the edge MLP ----------------
__global__ __launch_bounds__(256) void k_pair(const int* __restrict__ nstruct,
                                              const float* __restrict__ w1,
                                              const float* __restrict__ b1,
                                              int layer, int n_nodes) {
    __shared__ float sWs[70 * 64];
    __shared__ float sWd[70 * 64];
    const float* Wl = w1 + (size_t)layer * MSG_IN * 64;
    for (int i = threadIdx.x; i < 70 * 64; i += blockDim.x) {
        int r = i >> 6, j = i & 63;
        int rs = (r < 64) ? r : (128 + (r - 64));
        int rd = (r < 64) ? (64 + r) : (134 + (r - 64));
        sWs[i] = Wl[rs * 64 + j];
        sWd[i] = Wl[rd * 64 + j];
    }
    __syncthreads();
    const int lane = threadIdx.x & 31;
    const int wid  = blockIdx.x * (blockDim.x >> 5) + (threadIdx.x >> 5);
    const int nw   = gridDim.x * (blockDim.x >> 5);
    const float bd0 = b1[layer * 64 + lane], bd1 = b1[layer * 64 + lane + 32];
    const int ntiles = (n_nodes + 3) >> 2;
    for (int t = wid; t < ntiles; t += nw) {
        const int n0 = t * 4;
        float xr[4][2], as0[4], as1[4], ad0[4], ad1[4];
        float scr;
        {
            int nn = lane / 6, c = lane - nn * 6;
            int n = min(n0 + min(nn, 3), n_nodes - 1);
            scr = (lane < 24) ? (float)nstruct[n * SC_DIMS + c] : 0.f;
        }
#pragma unroll
        for (int nn = 0; nn < 4; nn++) {
            int n = min(n0 + nn, n_nodes - 1);
            xr[nn][0] = g_h[n * 64 + lane];
            xr[nn][1] = g_h[n * 64 + lane + 32];
            as0[nn] = 0.f; as1[nn] = 0.f; ad0[nn] = bd0; ad1[nn] = bd1;
        }
#pragma unroll
        for (int r = 0; r < 2; r++)
#pragma unroll
            for (int kk = 0; kk < 32; kk++) {
                int k = r * 32 + kk;
                float ws0 = sWs[k * 64 + lane], ws1 = sWs[k * 64 + lane + 32];
                float wd0 = sWd[k * 64 + lane], wd1 = sWd[k * 64 + lane + 32];
#pragma unroll
                for (int nn = 0; nn < 4; nn++) {
                    float xv = __shfl_sync(0xffffffffu, xr[nn][r], kk);
                    as0[nn] += xv * ws0; as1[nn] += xv * ws1;
                    ad0[nn] += xv * wd0; ad1[nn] += xv * wd1;
                }
            }
#pragma unroll
        for (int c = 0; c < 6; c++) {
            int k = 64 + c;
            float ws0 = sWs[k * 64 + lane], ws1 = sWs[k * 64 + lane + 32];
            float wd0 = sWd[k * 64 + lane], wd1 = sWd[k * 64 + lane + 32];
#pragma unroll
            for (int nn = 0; nn < 4; nn++) {
                float sv = __shfl_sync(0xffffffffu, scr, nn * 6 + c);
                as0[nn] += sv * ws0; as1[nn] += sv * ws1;
                ad0[nn] += sv * wd0; ad1[nn] += sv * wd1;
            }
        }
#pragma unroll
        for (int nn = 0; nn < 4; nn++) {
            int n = n0 + nn;
            if (n < n_nodes) {
                g_Ps[n * 64 + lane] = as0[nn]; g_Ps[n * 64 + lane + 32] = as1[nn];
                g_Pd[n * 64 + lane] = ad0[nn]; g_Pd[n * 64 + lane + 32] = ad1[nn];
            }
        }
    }
}

// ---------------- gather: agg[n] = sum_{e: dst=n} ew * relu(Ps[src]+Pd[n]+ef@E) ----------
// One warp per node. No atomics, no clears. Also emits wdeg[n].
__global__ __launch_bounds__(256) void k_gather(const float* __restrict__ ef,
                                                const float* __restrict__ w1,
                                                int layer, int n_nodes) {
    const int lane = threadIdx.x & 31;
    const int node = blockIdx.x * 8 + (threadIdx.x >> 5);
    // E = W1 rows [140:156), registers per lane
    float E0[16], E1[16];
    const float* Wb = w1 + ((size_t)layer * MSG_IN + 140) * 64;
#pragma unroll
    for (int k = 0; k < 16; k++) { E0[k] = Wb[k * 64 + lane]; E1[k] = Wb[k * 64 + lane + 32]; }
    if (node >= n_nodes) return;

    const int beg = g_ptr[node];
    const int cnt = g_cnt[node];
    const float pd0 = g_Pd[(size_t)node * 64 + lane];
    const float pd1 = g_Pd[(size_t)node * 64 + lane + 32];
    float acc0 = 0.f, acc1 = 0.f, wd = 0.f;

    int4 m = (cnt > 0) ? g_csre[beg] : make_int4(0, 0, 0, 0);
    for (int i = 0; i < cnt; i++) {
        int4 mn = (i + 1 < cnt) ? g_csre[beg + i + 1] : m;
        const float w = __int_as_float(m.z);
        float efv = (lane < 16) ? ef[(size_t)m.y * 16 + lane] : 0.f;
        float a0 = g_Ps[(size_t)m.x * 64 + lane]      + pd0;
        float a1 = g_Ps[(size_t)m.x * 64 + lane + 32] + pd1;
#pragma unroll
        for (int k = 0; k < 16; k++) {
            float v = __shfl_sync(0xffffffffu, efv, k);
            a0 += v * E0[k]; a1 += v * E1[k];
        }
        acc0 += fmaxf(a0, 0.f) * w;
        acc1 += fmaxf(a1, 0.f) * w;
        wd += w;
        m = mn;
    }
    g_agg[(size_t)node * 64 + lane]      = acc0;
    g_agg[(size_t)node * 64 + lane + 32] = acc1;
    if (lane == 0) g_wdeg[node] = wd;
}

// ---------------- upd = agg @ W2 + b2*wdeg   (in place into g_agg) ----------------
__global__ __launch_bounds__(256) void k_node_a(const float* __restrict__ w2,
                                                const float* __restrict__ b2,
                                                int layer, int n_nodes) {
    __shared__ float sW[64 * 64];
    const float* Wl = w2 + (size_t)layer * 64 * 64;
    for (int i = threadIdx.x; i < 64 * 64; i += blockDim.x) sW[i] = Wl[i];
    __syncthreads();
    const int lane = threadIdx.x & 31;
    const int wid  = blockIdx.x * (blockDim.x >> 5) + (threadIdx.x >> 5);
    const int nw   = gridDim.x * (blockDim.x >> 5);
    const float b0 = b2[layer * 64 + lane], b1 = b2[layer * 64 + lane + 32];
    const int ntiles = (n_nodes + 3) >> 2;
    for (int t = wid; t < ntiles; t += nw) {
        const int n0 = t * 4;
        float xr[4][2], a0[4], a1[4];
#pragma unroll
        for (int nn = 0; nn < 4; nn++) {
            int n = min(n0 + nn, n_nodes - 1);
            xr[nn][0] = g_agg[n * 64 + lane];
            xr[nn][1] = g_agg[n * 64 + lane + 32];
            float wd = g_wdeg[n];
            a0[nn] = b0 * wd; a1[nn] = b1 * wd;
        }
#pragma unroll
        for (int r = 0; r < 2; r++)
#pragma unroll
            for (int kk = 0; kk < 32; kk++) {
                const float* wr = &sW[(r * 32 + kk) * 64];
                float w0 = wr[lane], w1 = wr[lane + 32];
#pragma unroll
                for (int nn = 0; nn < 4; nn++) {
                    float xv = __shfl_sync(0xffffffffu, xr[nn][r], kk);
                    a0[nn] += xv * w0; a1[nn] += xv * w1;
                }
            }
#pragma unroll
        for (int nn = 0; nn < 4; nn++) {
            int n = n0 + nn;
            if (n < n_nodes) { g_agg[n * 64 + lane] = a0[nn]; g_agg[n * 64 + lane + 32] = a1[nn]; }
        }
    }
}

// ---------------- h = relu( relu(cat(h,upd)@U1 + ub1) @ U2 + ub2 )  (in place) -------------
__global__ __launch_bounds__(256) void k_node_bc(const float* __restrict__ u1,
                                                 const float* __restrict__ ub1,
                                                 const float* __restrict__ u2,
                                                 const float* __restrict__ ub2,
                                                 int layer, int n_nodes) {
    __shared__ float sU1[128 * 64];
    __shared__ float sU2[64 * 64];
    const float* U1l = u1 + (size_t)layer * 128 * 64;
    const float* U2l = u2 + (size_t)layer * 64 * 64;
    for (int i = threadIdx.x; i < 128 * 64; i += blockDim.x) sU1[i] = U1l[i];
    for (int i = threadIdx.x; i < 64 * 64; i += blockDim.x) sU2[i] = U2l[i];
    __syncthreads();
    const int lane = threadIdx.x & 31;
    const int wid  = blockIdx.x * (blockDim.x >> 5) + (threadIdx.x >> 5);
    const int nw   = gridDim.x * (blockDim.x >> 5);
    const float c10 = ub1[layer * 64 + lane], c11 = ub1[layer * 64 + lane + 32];
    const float c20 = ub2[layer * 64 + lane], c21 = ub2[layer * 64 + lane + 32];
    const int ntiles = (n_nodes + 3) >> 2;
    for (int t = wid; t < ntiles; t += nw) {
        const int n0 = t * 4;
        float hr[4][2], ur[4][2], a0[4], a1[4];
#pragma unroll
        for (int nn = 0; nn < 4; nn++) {
            int n = min(n0 + nn, n_nodes - 1);
            hr[nn][0] = g_h[n * 64 + lane];   hr[nn][1] = g_h[n * 64 + lane + 32];
            ur[nn][0] = g_agg[n * 64 + lane]; ur[nn][1] = g_agg[n * 64 + lane + 32];
            a0[nn] = c10; a1[nn] = c11;
        }
#pragma unroll
        for (int r = 0; r < 2; r++)
#pragma unroll
            for (int kk = 0; kk < 32; kk++) {
                const float* wr = &sU1[(r * 32 + kk) * 64];
                float w0 = wr[lane], w1 = wr[lane + 32];
#pragma unroll
                for (int nn = 0; nn < 4; nn++) {
                    float xv = __shfl_sync(0xffffffffu, hr[nn][r], kk);
                    a0[nn] += xv * w0; a1[nn] += xv * w1;
                }
            }
#pragma unroll
        for (int r = 0; r < 2; r++)
#pragma unroll
            for (int kk = 0; kk < 32; kk++) {
                const float* wr = &sU1[(64 + r * 32 + kk) * 64];
                float w0 = wr[lane], w1 = wr[lane + 32];
#pragma unroll
                for (int nn = 0; nn < 4; nn++) {
                    float xv = __shfl_sync(0xffffffffu, ur[nn][r], kk);
                    a0[nn] += xv * w0; a1[nn] += xv * w1;
                }
            }
#pragma unroll
        for (int nn = 0; nn < 4; nn++) {
            hr[nn][0] = fmaxf(a0[nn], 0.f);
            hr[nn][1] = fmaxf(a1[nn], 0.f);
            a0[nn] = c20; a1[nn] = c21;
        }
#pragma unroll
        for (int r = 0; r < 2; r++)
#pragma unroll
            for (int kk = 0; kk < 32; kk++) {
                const float* wr = &sU2[(r * 32 + kk) * 64];
                float w0 = wr[lane], w1 = wr[lane + 32];
#pragma unroll
                for (int nn = 0; nn < 4; nn++) {
                    float xv = __shfl_sync(0xffffffffu, hr[nn][r], kk);
                    a0[nn] += xv * w0; a1[nn] += xv * w1;
                }
            }
#pragma unroll
        for (int nn = 0; nn < 4; nn++) {
            int n = n0 + nn;
            if (n < n_nodes) {
                g_h[n * 64 + lane]      = fmaxf(a0[nn], 0.f);
                g_h[n * 64 + lane + 32] = fmaxf(a1[nn], 0.f);
            }
        }
    }
}

// ---------------- outputs: graph_feature (atomic segsum) + node_feature copy -------------
__global__ void k_final(const int* __restrict__ n2g, float* __restrict__ out,
                        int n_nodes, int gf_floats) {
    int i = blockIdx.x * blockDim.x + threadIdx.x;
    int total = n_nodes * 16;
    if (i >= total) return;
    int n = i >> 4, q = i & 15;
    float4 v = ((const float4*)g_h)[i];
    ((float4*)out)[(gf_floats >> 2) + i] = v;   // node_feature block
    int g = n2g[n];
    red_add_v4(out + g * 64 + q * 4, v);        // graph_feature block
}

// ============================ launcher ============================
extern "C" void kernel_launch(void* const* d_in, const int* in_sizes, int n_in,
                              void* d_out, int out_size) {
    const float* x     = (const float*)d_in[0];
    const int*   el    = (const int*)d_in[1];
    const int*   ns    = (const int*)d_in[2];
    const float* ef    = (const float*)d_in[3];
    const float* ew    = (const float*)d_in[4];
    const int*   n2g   = (const int*)d_in[5];
    const float* lin_w = (const float*)d_in[7];
    const float* lin_b = (const float*)d_in[8];
    const float* mw1   = (const float*)d_in[9];
    const float* mb1   = (const float*)d_in[10];
    const float* mw2   = (const float*)d_in[11];
    const float* mb2   = (const float*)d_in[12];
    const float* uw1   = (const float*)d_in[13];
    const float* ub1   = (const float*)d_in[14];
    const float* uw2   = (const float*)d_in[15];
    const float* ub2   = (const float*)d_in[16];

    const int n_nodes = in_sizes[0] / HID;
    const int n_edges = in_sizes[1] / 2;
    const int gf      = out_size - n_nodes * HID;
    float* out = (float*)d_out;

    auto cdiv = [](int a, int b) { return (a + b - 1) / b; };
    const int nb_scan = cdiv(n_nodes, SCHUNK);

    // CSR build (once per launch; reused by both layers)
    k_clear_cnt<<<cdiv(n_nodes, 256), 256>>>(n_nodes);
    k_hist<<<cdiv(n_edges, 256), 256>>>(el, n_edges);
    k_scan1<<<nb_scan, 256>>>(n_nodes);
    k_scan2<<<1, 32>>>(nb_scan);
    k_scan3<<<nb_scan, 256>>>(n_nodes);
    k_scatter<<<cdiv(n_edges, 256), 256>>>(el, ew, n_edges);

    k_clear_out<<<cdiv(gf, 256), 256>>>(out, gf);
    k_lin<<<1184, 256>>>(x, lin_w, lin_b, n_nodes);

    for (int l = 0; l < 2; l++) {
        k_pair<<<740, 256>>>(ns, mw1, mb1, l, n_nodes);
        k_gather<<<cdiv(n_nodes, 8), 256>>>(ef, mw1, l, n_nodes);
        k_node_a<<<1184, 256>>>(mw2, mb2, l, n_nodes);
        k_node_bc<<<592, 256>>>(uw1, ub1, uw2, ub2, l, n_nodes);
    }

    k_final<<<cdiv(n_nodes * 16, 256), 256>>>(n2g, out, n_nodes, gf);
}